// round 16
// baseline (speedup 1.0000x reference)
#include <cuda_runtime.h>
#include <cuda_fp16.h>
#include <math.h>
#include <cstdint>

#define LL    4096
#define DD    64
#define MODES 64
#define BH    64
#define MM    128
#define NSPLIT 4
#define SCALE 0.125f

// ---------------- globals (no allocation) ----------------
__device__ float2   g_tab[LL];                      // cos/sin(2*pi*r/4096), fp32-exact
__device__ int      g_perm[3][64];                  // parity-sorted mode order per tensor
__device__ int      g_sclass[3][4];                 // strip class: 0=even 1=odd 2=mixed
__device__ int      g_vmap[64];                     // sigma_v^-1 o sigma_k
__device__ uint32_t g_WfPHi[3][8][2][64][32][4];    // fwd basis frags (K=1024), parity variant
__device__ uint32_t g_WfPLo[3][8][2][64][32][4];
__device__ uint32_t g_WiCcHi[128][4][32][4];        // inv cos basis frags (x1024 scaled)
__device__ uint32_t g_WiCcLo[128][4][32][4];
__device__ uint32_t g_WiCsHi[128][4][32][4];        // inv -sin basis frags
__device__ uint32_t g_WiCsLo[128][4][32][4];
__device__ float    g_F[3][NSPLIT][BH][MM][DD];     // split-K partials (storage mode order)
__device__ float    g_V2[BH][MM][DD];               // post-attention values

// ---------------- packed helpers ----------------
__device__ __forceinline__ uint64_t pk2(float lo, float hi) {
    uint64_t r;
    asm("mov.b64 %0, {%1, %2};" : "=l"(r) : "f"(lo), "f"(hi));
    return r;
}
__device__ __forceinline__ void unpk2(uint64_t p, float& lo, float& hi) {
    asm("mov.b64 {%0, %1}, %2;" : "=f"(lo), "=f"(hi) : "l"(p));
}
__device__ __forceinline__ uint64_t addx2(uint64_t a, uint64_t b) {
    uint64_t r;
    asm("add.rn.f32x2 %0, %1, %2;" : "=l"(r) : "l"(a), "l"(b));
    return r;
}
__device__ __forceinline__ uint64_t fmax2(uint64_t a, uint64_t b, uint64_t c) {
    uint64_t r;
    asm("fma.rn.f32x2 %0, %1, %2, %3;" : "=l"(r) : "l"(a), "l"(b), "l"(c));
    return r;
}
__device__ __forceinline__ void split2h_f(float a, float b, uint32_t& h, uint32_t& l) {
    uint32_t hp;
    asm("cvt.rn.f16x2.f32 %0, %1, %2;" : "=r"(hp) : "f"(b), "f"(a));
    __half2 hh = *reinterpret_cast<__half2*>(&hp);
    float2 f = __half22float2(hh);
    asm("cvt.rn.f16x2.f32 %0, %1, %2;" : "=r"(l) : "f"(b - f.y), "f"(a - f.x));
    h = hp;
}
__device__ __forceinline__ void split2h_pk(uint64_t p, uint32_t& h, uint32_t& l) {
    float a, b;
    unpk2(p, a, b);
    split2h_f(a, b, h, l);
}
__device__ __forceinline__ void mma16816h(float* c, const uint4& a, const uint2& b) {
    asm volatile(
        "mma.sync.aligned.m16n8k16.row.col.f32.f16.f16.f32 "
        "{%0,%1,%2,%3}, {%4,%5,%6,%7}, {%8,%9}, {%0,%1,%2,%3};"
        : "+f"(c[0]), "+f"(c[1]), "+f"(c[2]), "+f"(c[3])
        : "r"(a.x), "r"(a.y), "r"(a.z), "r"(a.w), "r"(b.x), "r"(b.y));
}

// ---------------- kernel 0: phase table + permutations ----------------
__global__ __launch_bounds__(256) void tab_kernel(const int* __restrict__ iq,
                                                  const int* __restrict__ ik,
                                                  const int* __restrict__ iv) {
    int r = blockIdx.x * blockDim.x + threadIdx.x;
    if (r < LL) {
        float s, c;
        sincospif((float)r * (1.0f / 2048.0f), &s, &c);
        g_tab[r] = make_float2(c, s);
    }
    if (blockIdx.x == 0 && threadIdx.x == 0) {
        for (int t = 0; t < 3; t++) {
            const int* ix = (t == 0) ? iq : ((t == 1) ? ik : iv);
            int pm[64], ne = 0;
            for (int i = 0; i < 64; i++) if ((ix[i] & 1) == 0) pm[ne++] = i;
            int no = ne;
            for (int i = 0; i < 64; i++) if (ix[i] & 1) pm[no++] = i;
            for (int i = 0; i < 64; i++) g_perm[t][i] = pm[i];
            for (int s4 = 0; s4 < 4; s4++) {
                int st0 = s4 * 16, st1 = st0 + 15;
                g_sclass[t][s4] = (st1 < ne) ? 0 : ((st0 >= ne) ? 1 : 2);
            }
        }
        int ipv[64];
        for (int i = 0; i < 64; i++) ipv[g_perm[2][i]] = i;
        for (int s4 = 0; s4 < 64; s4++) g_vmap[s4] = ipv[g_perm[1][s4]];
    }
}

// ---------------- kernel 1: build fragment-packed bases (fwd + inv merged) --------
#define FWDN (3 * 8 * 2 * 64 * 32 * 4)   // 393216
#define INVN (2 * 128 * 4 * 32 * 4)      // 131072

__global__ __launch_bounds__(256) void build_packed(const int* __restrict__ iq,
                                                    const int* __restrict__ ik,
                                                    const int* __restrict__ iv) {
    for (int gid = blockIdx.x * blockDim.x + threadIdx.x; gid < FWDN + INVN;
         gid += gridDim.x * blockDim.x) {
        if (gid < FWDN) {
            int r    = gid & 3;
            int lane = (gid >> 2) & 31;
            int ks   = (gid >> 7) & 63;
            int vv   = (gid >> 13) & 1;
            int s    = (gid >> 14) & 7;
            int t    = gid >> 17;
            int m_local = s * 16 + (r & 1) * 8 + (lane >> 2);
            const int* ix = (t == 0) ? iq : ((t == 1) ? ik : iv);
            int f = ix[g_perm[t][m_local & 63]];
            float v0 = 0.0f, v1 = 0.0f;
            if ((f & 1) == vv) {
                int k = ks * 16 + ((r >> 1) & 1) * 8 + (lane & 3) * 2;   // n in [0,1024)
                int r1 = (f * k) & (LL - 1);
                int r2 = (r1 + f) & (LL - 1);
                float2 c1 = g_tab[r1], c2 = g_tab[r2];
                v0 = (m_local < MODES) ? c1.x : -c1.y;
                v1 = (m_local < MODES) ? c2.x : -c2.y;
            }
            uint32_t h, l;
            split2h_f(v0, v1, h, l);
            g_WfPHi[t][s][vv][ks][lane][r] = h;
            g_WfPLo[t][s][vv][ks][lane][r] = l;
        } else {
            int g2   = gid - FWDN;
            int r    = g2 & 3;
            int lane = (g2 >> 2) & 31;
            int ks   = (g2 >> 7) & 3;
            int st   = (g2 >> 9) & 127;
            int arr  = (g2 >> 16) & 1;       // 0 = cos, 1 = -sin
            int n  = st * 16 + (r & 1) * 8 + (lane >> 2);          // [0,2048)
            int k  = ks * 16 + ((r >> 1) & 1) * 8 + (lane & 3) * 2; // [0,64)
            float v0, v1;
            {
                int fb = g_perm[0][k];
                float cs = (fb == 0) ? 0.25f : 0.5f;   // 1024 * (1 or 2)/4096
                float2 c1 = g_tab[(fb * n) & (LL - 1)];
                v0 = arr ? (-cs * c1.y) : (cs * c1.x);
            }
            {
                int fb = g_perm[0][k + 1];
                float cs = (fb == 0) ? 0.25f : 0.5f;
                float2 c1 = g_tab[(fb * n) & (LL - 1)];
                v1 = arr ? (-cs * c1.y) : (cs * c1.x);
            }
            uint32_t h, l;
            split2h_f(v0, v1, h, l);
            if (arr == 0) { g_WiCcHi[st][ks][lane][r] = h; g_WiCcLo[st][ks][lane][r] = l; }
            else          { g_WiCsHi[st][ks][lane][r] = h; g_WiCsLo[st][ks][lane][r] = l; }
        }
    }
}

// ---------------- kernel 2: forward DFT (fold-by-4, H/L-interleaved smem) ---------
// Smem B arrays interleave (hi,lo) per column: word = row*80 + col*2 (+0=H, +1=L).
// Producer: one STS.64 per (array,i). Consumer: one LDS.128 yields bH+bL.
#define FWD_ARR_WORDS 5120   // 64 rows * 80 words
__global__ __launch_bounds__(512, 2) void fwd_mma(const float* __restrict__ q,
                                                  const float* __restrict__ k_,
                                                  const float* __restrict__ v_,
                                                  const int* __restrict__ iq,
                                                  const int* __restrict__ ik,
                                                  const int* __restrict__ iv) {
    extern __shared__ uint32_t dsm[];
    const int split = blockIdx.x, bh = blockIdx.y, t = blockIdx.z;
    const float* xb = ((t == 0) ? q : ((t == 1) ? k_ : v_)) + (size_t)bh * LL * DD;
    const int tid = threadIdx.x, warp = tid >> 5, lane = tid & 31;
    const int g = lane >> 2, tq = lane & 3;
    const int s = ((warp >> 1) + bh + split) & 7;   // rotated strip per warp-pair
    const int jh = warp & 1;                        // j-half
    const int cls = g_sclass[t][s & 3];
    const int vbase = (s >= 4) ? 2 : 0;
    const int p  = tid >> 4;                        // k-pair index 0..31
    const int dg = tid & 15;                        // d-group
    const int wsw = ((p >> 3) << 3) + ((p & 3) << 1) + ((p >> 2) & 1);
    const int colp = wsw ^ (dg << 1);               // producer swizzled column

#define FARR2(v_) (dsm + (v_) * FWD_ARR_WORDS)

    float acc[4][4];
#pragma unroll
    for (int j = 0; j < 4; j++)
#pragma unroll
        for (int i = 0; i < 4; i++) acc[j][i] = 0.0f;

    const uint64_t M1 = pk2(-1.0f, -1.0f);

    for (int ch = 0; ch < 4; ch++) {
        const int nn = split * 256 + ch * 64 + 2 * p;   // n (first of pair), in [0,1024)
        {
            const int mi0 = (LL - nn) & (LL - 1);
            const int mi1 = LL - 1 - nn;
            const int dof = dg * 4;
            const float* pa  = xb + (size_t)nn * DD + dof;
            const float* pr0 = xb + (size_t)mi0 * DD + dof;
            const float* pr1 = xb + (size_t)mi1 * DD + dof;
            const float* pc  = xb + (size_t)(2048 + nn) * DD + dof;
            const float* pd0 = xb + (size_t)(2048 - nn) * DD + dof;
            const float* pd1 = xb + (size_t)(2047 - nn) * DD + dof;
            float4 x0;
            x0 = *(const float4*)(pa);
            float Aa[4] = {x0.x, x0.y, x0.z, x0.w};
            x0 = *(const float4*)(pa + DD);
            float Ab[4] = {x0.x, x0.y, x0.z, x0.w};
            x0 = *(const float4*)(pr0);
            float Ra[4] = {x0.x, x0.y, x0.z, x0.w};
            x0 = *(const float4*)(pr1);
            float Rb[4] = {x0.x, x0.y, x0.z, x0.w};
            x0 = *(const float4*)(pc);
            float Ca[4] = {x0.x, x0.y, x0.z, x0.w};
            x0 = *(const float4*)(pc + DD);
            float Cb[4] = {x0.x, x0.y, x0.z, x0.w};
            x0 = *(const float4*)(pd0);
            float Da[4] = {x0.x, x0.y, x0.z, x0.w};
            x0 = *(const float4*)(pd1);
            float Db[4] = {x0.x, x0.y, x0.z, x0.w};

            uint32_t* B0 = FARR2(0);
            uint32_t* B1 = FARR2(1);
            uint32_t* B2 = FARR2(2);
            uint32_t* B3 = FARR2(3);
#pragma unroll
            for (int i = 0; i < 4; i++) {
                uint64_t A = pk2(Aa[i], Ab[i]);
                uint64_t R = pk2(Ra[i], Rb[i]);
                uint64_t C = pk2(Ca[i], Cb[i]);
                uint64_t D = pk2(Da[i], Db[i]);
                uint64_t u = addx2(A, R);
                uint64_t wv = fmax2(R, M1, A);
                uint64_t y = addx2(C, D);
                uint64_t z = fmax2(D, M1, C);
                if (nn == 0) {   // half-weight on n=0 sample (lo half of pair)
                    float ua, ub, ya, yb;
                    unpk2(u, ua, ub); ua *= 0.5f; u = pk2(ua, ub);
                    unpk2(y, ya, yb); ya *= 0.5f; y = pk2(ya, yb);
                }
                uint64_t b0 = addx2(u, y);
                uint64_t b1 = fmax2(y, M1, u);
                uint64_t b2 = addx2(wv, z);
                uint64_t b3 = fmax2(z, M1, wv);
                const int row = dg * 4 + i;          // d index
                const int adr = row * 80 + colp * 2;
                uint32_t h, l;
                split2h_pk(b0, h, l); *(uint2*)&B0[adr] = make_uint2(h, l);
                split2h_pk(b1, h, l); *(uint2*)&B1[adr] = make_uint2(h, l);
                split2h_pk(b2, h, l); *(uint2*)&B2[adr] = make_uint2(h, l);
                split2h_pk(b3, h, l); *(uint2*)&B3[adr] = make_uint2(h, l);
            }
        }
        __syncthreads();
        const int ksg = split * 16 + ch * 4;
#pragma unroll
        for (int ks4 = 0; ks4 < 4; ks4++) {
            if (cls != 1) {
                uint4 aH = *(const uint4*)&g_WfPHi[t][s][0][ksg + ks4][lane][0];
                uint4 aL = *(const uint4*)&g_WfPLo[t][s][0][ksg + ks4][lane][0];
                const uint32_t* B_ = FARR2(vbase + 0);
#pragma unroll
                for (int j = 0; j < 4; j++) {
                    const int jg = jh * 4 + j;
                    const int rowX = jg * 8 + g;
                    const int csw = (ks4 * 8 + 2 * tq) ^ ((rowX >> 2) << 1);
                    uint4 x = *(const uint4*)&B_[rowX * 80 + csw * 2];
                    uint2 bH = make_uint2(x.x, x.z);
                    uint2 bL = make_uint2(x.y, x.w);
                    mma16816h(acc[j], aH, bH);
                    mma16816h(acc[j], aH, bL);
                    mma16816h(acc[j], aL, bH);
                }
            }
            if (cls != 0) {
                uint4 aH = *(const uint4*)&g_WfPHi[t][s][1][ksg + ks4][lane][0];
                uint4 aL = *(const uint4*)&g_WfPLo[t][s][1][ksg + ks4][lane][0];
                const uint32_t* B_ = FARR2(vbase + 1);
#pragma unroll
                for (int j = 0; j < 4; j++) {
                    const int jg = jh * 4 + j;
                    const int rowX = jg * 8 + g;
                    const int csw = (ks4 * 8 + 2 * tq) ^ ((rowX >> 2) << 1);
                    uint4 x = *(const uint4*)&B_[rowX * 80 + csw * 2];
                    uint2 bH = make_uint2(x.x, x.z);
                    uint2 bL = make_uint2(x.y, x.w);
                    mma16816h(acc[j], aH, bH);
                    mma16816h(acc[j], aH, bL);
                    mma16816h(acc[j], aL, bH);
                }
            }
        }
        __syncthreads();
    }

    const int m0 = s * 16;
    // rank-1 correction for samples x[1024], x[3072] (added once, in split 0)
    if (split == 0) {
        const int* ix = (t == 0) ? iq : ((t == 1) ? ik : iv);
        const bool is_im = (s >= 4);
        int f0 = ix[g_perm[t][(m0 + g) & 63]];
        int f1 = ix[g_perm[t][(m0 + g + 8) & 63]];
        float s0f, s1f;
        if (!is_im) {
            s0f = (f0 & 1) ? 0.0f : (((f0 >> 1) & 1) ? -1.0f : 1.0f);
            s1f = (f1 & 1) ? 0.0f : (((f1 >> 1) & 1) ? -1.0f : 1.0f);
        } else {
            s0f = (f0 & 1) ? (((f0 & 3) == 1) ? -1.0f : 1.0f) : 0.0f;
            s1f = (f1 & 1) ? (((f1 & 3) == 1) ? -1.0f : 1.0f) : 0.0f;
        }
        const float sgn = is_im ? -1.0f : 1.0f;
#pragma unroll
        for (int j = 0; j < 4; j++) {
            const int jg = jh * 4 + j;
            int d0 = jg * 8 + 2 * tq;
            float2 u1 = *(const float2*)(xb + (size_t)1024 * DD + d0);
            float2 u3 = *(const float2*)(xb + (size_t)3072 * DD + d0);
            float uc0 = u1.x + sgn * u3.x;
            float uc1 = u1.y + sgn * u3.y;
            acc[j][0] += s0f * uc0; acc[j][1] += s0f * uc1;
            acc[j][2] += s1f * uc0; acc[j][3] += s1f * uc1;
        }
    }
#pragma unroll
    for (int j = 0; j < 4; j++) {
        const int jg = jh * 4 + j;
        float* dst = &g_F[t][split][bh][m0 + g][jg * 8 + 2 * tq];
        *(float2*)dst = make_float2(acc[j][0], acc[j][1]);
        *(float2*)(dst + 8 * DD) = make_float2(acc[j][2], acc[j][3]);
    }
#undef FARR2
}

// ---------------- kernel 3: complex attention (mode-split 4-way, 256 threads) -----
// Conflict-free column remap retained (columns tn + 16*j). Grid (BH,4) = 256 blocks.
#define SP 65
__device__ __forceinline__ float4 sum_splits4(const float* base) {
    const size_t STR = (size_t)BH * MM * DD;
    float4 a = *(const float4*)(base);
#pragma unroll
    for (int s = 1; s < NSPLIT; s++) {
        float4 b = *(const float4*)(base + s * STR);
        a.x += b.x; a.y += b.y; a.z += b.z; a.w += b.w;
    }
    return a;
}

__global__ __launch_bounds__(256) void attn_kernel() {
    extern __shared__ float sm[];
    float* Ks = sm;                 // [128][65]
    float* Vs = Ks + MM * SP;       // [128][65]
    float* Qs = Vs + MM * SP;       // [32][65]  (16 re + 16 im)
    float* SR = Qs + 32 * SP;       // [16][65]
    float* SI = SR + 16 * SP;       // [16][65]

    const int bh = blockIdx.x, ms = blockIdx.y;   // ms in {0..3}
    const int tid = threadIdx.x;

    for (int e = tid; e < MM * 16; e += 256) {
        const int r = e >> 4, d4 = (e & 15) * 4;
        float4 kk = sum_splits4(&g_F[1][0][bh][r][d4]);
        int vrow = ((r >= 64) ? 64 : 0) + __ldg(&g_vmap[r & 63]);
        float4 vv = sum_splits4(&g_F[2][0][bh][vrow][d4]);
        float* kd = &Ks[r * SP + d4];
        kd[0] = kk.x; kd[1] = kk.y; kd[2] = kk.z; kd[3] = kk.w;
        float* vd = &Vs[r * SP + d4];
        vd[0] = vv.x; vd[1] = vv.y; vd[2] = vv.z; vd[3] = vv.w;
    }
    for (int e = tid; e < 32 * 16; e += 256) {
        const int r = e >> 4, d4 = (e & 15) * 4;
        int qrow = (r < 16) ? (ms * 16 + r) : (64 + ms * 16 + (r - 16));
        float4 qq = sum_splits4(&g_F[0][0][bh][qrow][d4]);
        float* qd = &Qs[r * SP + d4];
        qd[0] = qq.x; qd[1] = qq.y; qd[2] = qq.z; qd[3] = qq.w;
    }
    __syncthreads();

    const int tm = tid >> 4;   // mode row 0..15
    const int tn = tid & 15;

    {
        float re[4], im[4];
#pragma unroll
        for (int j = 0; j < 4; j++) { re[j] = 0.f; im[j] = 0.f; }
        for (int d = 0; d < DD; d++) {
            float qr = Qs[tm * SP + d];
            float qi = Qs[(16 + tm) * SP + d];
#pragma unroll
            for (int j = 0; j < 4; j++) {
                const int kc = tn + 16 * j;
                float kr = Ks[kc * SP + d];
                float ki = Ks[(64 + kc) * SP + d];
                re[j] = fmaf(qr, kr, re[j]);
                re[j] = fmaf(-qi, ki, re[j]);
                im[j] = fmaf(qr, ki, im[j]);
                im[j] = fmaf(qi, kr, im[j]);
            }
        }
#pragma unroll
        for (int j = 0; j < 4; j++) {
            const float x  = re[j] * SCALE;
            const float y  = im[j] * SCALE;
            const float x2 = 2.0f * x;
            float tr, ti;
            if (fabsf(x2) > 80.0f) {
                tr = (x > 0.0f) ? 1.0f : -1.0f;
                ti = 0.0f;
            } else {
                const float y2 = 2.0f * y;
                const float dn = coshf(x2) + cosf(y2);
                tr = sinhf(x2) / dn;
                ti = sinf(y2) / dn;
            }
            SR[tm * SP + tn + 16 * j] = tr;
            SI[tm * SP + tn + 16 * j] = ti;
        }
    }
    __syncthreads();

    {
        float vr[4], vi[4];
#pragma unroll
        for (int j = 0; j < 4; j++) { vr[j] = 0.f; vi[j] = 0.f; }
        for (int n = 0; n < MODES; n++) {
            float sr = SR[tm * SP + n];
            float si = SI[tm * SP + n];
#pragma unroll
            for (int j = 0; j < 4; j++) {
                const int vc = tn + 16 * j;
                float br = Vs[n * SP + vc];
                float bi = Vs[(64 + n) * SP + vc];
                vr[j] = fmaf(sr, br, vr[j]);
                vr[j] = fmaf(-si, bi, vr[j]);
                vi[j] = fmaf(sr, bi, vi[j]);
                vi[j] = fmaf(si, br, vi[j]);
            }
        }
#pragma unroll
        for (int j = 0; j < 4; j++) {
            const int vc = tn + 16 * j;
            g_V2[bh][ms * 16 + tm][vc]      = vr[j];
            g_V2[bh][64 + ms * 16 + tm][vc] = vi[j];
        }
    }
}

// ---------------- kernel 4: inverse transform (mirror trick, fp16 3-pass) ---------
#define ISC (1.0f / 1024.0f)
__global__ __launch_bounds__(256) void inv_mma(float* __restrict__ out) {
    __shared__ uint32_t BsH[64][72];
    __shared__ uint32_t BsL[64][72];
    const int nt = blockIdx.x, bh = blockIdx.y;
    const int tid = threadIdx.x, warp = tid >> 5, lane = tid & 31;
    const int g = lane >> 2, tq = lane & 3;

    {
        const int pr = tid & 63, quad = tid >> 6;
        const int w = ((pr >> 3) << 3) + ((pr & 3) << 1) + ((pr >> 2) & 1);
        const float* r0 = &g_V2[bh][2 * pr][quad * 16];
#pragma unroll
        for (int c4 = 0; c4 < 4; c4++) {
            float4 a4 = *(const float4*)(r0 + c4 * 4);
            float4 b4 = *(const float4*)(r0 + DD + c4 * 4);
            float ar[4] = {a4.x, a4.y, a4.z, a4.w};
            float br[4] = {b4.x, b4.y, b4.z, b4.w};
#pragma unroll
            for (int i = 0; i < 4; i++) {
                int d = quad * 16 + c4 * 4 + i;
                uint32_t h, l;
                split2h_f(ar[i] * ISC, br[i] * ISC, h, l);
                BsH[d][w] = h;
                BsL[d][w] = l;
            }
        }
    }
    __syncthreads();

    float accC[8][4], accS[8][4];
#pragma unroll
    for (int j = 0; j < 8; j++)
#pragma unroll
        for (int i = 0; i < 4; i++) { accC[j][i] = 0.0f; accS[j][i] = 0.0f; }

    const int st = nt * 8 + warp;
#pragma unroll
    for (int ks = 0; ks < 4; ks++) {
        uint4 aHc = *(const uint4*)&g_WiCcHi[st][ks][lane][0];
        uint4 aLc = *(const uint4*)&g_WiCcLo[st][ks][lane][0];
        uint4 aHs = *(const uint4*)&g_WiCsHi[st][ks][lane][0];
        uint4 aLs = *(const uint4*)&g_WiCsLo[st][ks][lane][0];
#pragma unroll
        for (int j = 0; j < 8; j++) {
            uint2 bHc = *(const uint2*)&BsH[j * 8 + g][ks * 8 + 2 * tq];
            uint2 bLc = *(const uint2*)&BsL[j * 8 + g][ks * 8 + 2 * tq];
            uint2 bHs = *(const uint2*)&BsH[j * 8 + g][(ks + 4) * 8 + 2 * tq];
            uint2 bLs = *(const uint2*)&BsL[j * 8 + g][(ks + 4) * 8 + 2 * tq];
            mma16816h(accC[j], aHc, bHc);
            mma16816h(accC[j], aHc, bLc);
            mma16816h(accC[j], aLc, bHc);
            mma16816h(accS[j], aHs, bHs);
            mma16816h(accS[j], aHs, bLs);
            mma16816h(accS[j], aLs, bHs);
        }
    }

    const int n0r = nt * 128 + warp * 16;
    float* ob = out + (size_t)bh * LL * DD;
#pragma unroll
    for (int j = 0; j < 8; j++) {
        const int d0 = j * 8 + 2 * tq;
        const int na = n0r + g, nb = n0r + g + 8;
        *(float2*)(ob + (size_t)na * DD + d0) =
            make_float2(accC[j][0] + accS[j][0], accC[j][1] + accS[j][1]);
        if (na != 0)
            *(float2*)(ob + (size_t)(LL - na) * DD + d0) =
                make_float2(accC[j][0] - accS[j][0], accC[j][1] - accS[j][1]);
        *(float2*)(ob + (size_t)nb * DD + d0) =
            make_float2(accC[j][2] + accS[j][2], accC[j][3] + accS[j][3]);
        *(float2*)(ob + (size_t)(LL - nb) * DD + d0) =
            make_float2(accC[j][2] - accS[j][2], accC[j][3] - accS[j][3]);
    }
    // out[2048] = sum_k c_k * (-1)^{f_k} * Vr[k][d]   (sin term = 0)
    if (nt == 0 && tid < 64) {
        const int d = tid;
        float sum = 0.0f;
#pragma unroll 8
        for (int k = 0; k < 64; k++) {
            int fb = g_perm[0][k];
            float c = (fb == 0) ? (1.0f / 4096.0f) : (2.0f / 4096.0f);
            float sg = (fb & 1) ? -c : c;
            sum += sg * g_V2[bh][k][d];
        }
        ob[(size_t)2048 * DD + d] = sum;
    }
}

// ---------------- entry point ----------------
extern "C" void kernel_launch(void* const* d_in, const int* in_sizes, int n_in,
                              void* d_out, int out_size) {
    const float* q  = (const float*)d_in[0];
    const float* k  = (const float*)d_in[1];
    const float* v  = (const float*)d_in[2];
    const int* iq   = (const int*)d_in[3];
    const int* ik   = (const int*)d_in[4];
    const int* iv   = (const int*)d_in[5];
    float* out      = (float*)d_out;

    tab_kernel<<<16, 256>>>(iq, ik, iv);            // idx 0
    build_packed<<<1024, 256>>>(iq, ik, iv);        // idx 1

    const int fwd_smem = 4 * FWD_ARR_WORDS * 4;   // 81920 B
    cudaFuncSetAttribute(fwd_mma, cudaFuncAttributeMaxDynamicSharedMemorySize, fwd_smem);
    fwd_mma<<<dim3(NSPLIT, BH, 3), 512, fwd_smem>>>(q, k, v, iq, ik, iv);   // idx 2

    const int attn_smem = (2 * MM + 32 + 2 * 16) * SP * (int)sizeof(float);  // 83200 B
    cudaFuncSetAttribute(attn_kernel, cudaFuncAttributeMaxDynamicSharedMemorySize, attn_smem);
    attn_kernel<<<dim3(BH, 4), 256, attn_smem>>>();                          // idx 3

    inv_mma<<<dim3(16, 64), 256>>>(out);                                     // idx 4
}

// round 17
// speedup vs baseline: 1.0687x; 1.0687x over previous
#include <cuda_runtime.h>
#include <cuda_fp16.h>
#include <math.h>
#include <cstdint>

#define LL    4096
#define DD    64
#define MODES 64
#define BH    64
#define MM    128
#define NSPLIT 4
#define SCALE 0.125f

// ---------------- globals (no allocation) ----------------
__device__ float2   g_tab[LL];                      // cos/sin(2*pi*r/4096), fp32-exact
__device__ int      g_perm[3][64];                  // parity-sorted mode order per tensor
__device__ int      g_sclass[3][4];                 // strip class: 0=even 1=odd 2=mixed
__device__ int      g_vmap[64];                     // sigma_v^-1 o sigma_k
__device__ uint32_t g_WfPHi[3][8][2][64][32][4];    // fwd basis frags (K=1024), parity variant
__device__ uint32_t g_WfPLo[3][8][2][64][32][4];
__device__ uint32_t g_WiCcHi[128][4][32][4];        // inv cos basis frags (x1024 scaled)
__device__ uint32_t g_WiCcLo[128][4][32][4];
__device__ uint32_t g_WiCsHi[128][4][32][4];        // inv -sin basis frags
__device__ uint32_t g_WiCsLo[128][4][32][4];
__device__ float    g_F[3][NSPLIT][BH][MM][DD];     // split-K partials (storage mode order)
__device__ float    g_V2[BH][MM][DD];               // post-attention values

// ---------------- packed helpers ----------------
__device__ __forceinline__ uint64_t pk2(float lo, float hi) {
    uint64_t r;
    asm("mov.b64 %0, {%1, %2};" : "=l"(r) : "f"(lo), "f"(hi));
    return r;
}
__device__ __forceinline__ void unpk2(uint64_t p, float& lo, float& hi) {
    asm("mov.b64 {%0, %1}, %2;" : "=f"(lo), "=f"(hi) : "l"(p));
}
__device__ __forceinline__ uint64_t addx2(uint64_t a, uint64_t b) {
    uint64_t r;
    asm("add.rn.f32x2 %0, %1, %2;" : "=l"(r) : "l"(a), "l"(b));
    return r;
}
__device__ __forceinline__ uint64_t fmax2(uint64_t a, uint64_t b, uint64_t c) {
    uint64_t r;
    asm("fma.rn.f32x2 %0, %1, %2, %3;" : "=l"(r) : "l"(a), "l"(b), "l"(c));
    return r;
}
__device__ __forceinline__ void split2h_f(float a, float b, uint32_t& h, uint32_t& l) {
    uint32_t hp;
    asm("cvt.rn.f16x2.f32 %0, %1, %2;" : "=r"(hp) : "f"(b), "f"(a));
    __half2 hh = *reinterpret_cast<__half2*>(&hp);
    float2 f = __half22float2(hh);
    asm("cvt.rn.f16x2.f32 %0, %1, %2;" : "=r"(l) : "f"(b - f.y), "f"(a - f.x));
    h = hp;
}
__device__ __forceinline__ void split2h_pk(uint64_t p, uint32_t& h, uint32_t& l) {
    float a, b;
    unpk2(p, a, b);
    split2h_f(a, b, h, l);
}
__device__ __forceinline__ void mma16816h(float* c, const uint4& a, const uint2& b) {
    asm volatile(
        "mma.sync.aligned.m16n8k16.row.col.f32.f16.f16.f32 "
        "{%0,%1,%2,%3}, {%4,%5,%6,%7}, {%8,%9}, {%0,%1,%2,%3};"
        : "+f"(c[0]), "+f"(c[1]), "+f"(c[2]), "+f"(c[3])
        : "r"(a.x), "r"(a.y), "r"(a.z), "r"(a.w), "r"(b.x), "r"(b.y));
}

// ---------------- kernel 0: phase table + permutations ----------------
__global__ __launch_bounds__(256) void tab_kernel(const int* __restrict__ iq,
                                                  const int* __restrict__ ik,
                                                  const int* __restrict__ iv) {
    int r = blockIdx.x * blockDim.x + threadIdx.x;
    if (r < LL) {
        float s, c;
        sincospif((float)r * (1.0f / 2048.0f), &s, &c);
        g_tab[r] = make_float2(c, s);
    }
    if (blockIdx.x == 0 && threadIdx.x == 0) {
        for (int t = 0; t < 3; t++) {
            const int* ix = (t == 0) ? iq : ((t == 1) ? ik : iv);
            int pm[64], ne = 0;
            for (int i = 0; i < 64; i++) if ((ix[i] & 1) == 0) pm[ne++] = i;
            int no = ne;
            for (int i = 0; i < 64; i++) if (ix[i] & 1) pm[no++] = i;
            for (int i = 0; i < 64; i++) g_perm[t][i] = pm[i];
            for (int s4 = 0; s4 < 4; s4++) {
                int st0 = s4 * 16, st1 = st0 + 15;
                g_sclass[t][s4] = (st1 < ne) ? 0 : ((st0 >= ne) ? 1 : 2);
            }
        }
        int ipv[64];
        for (int i = 0; i < 64; i++) ipv[g_perm[2][i]] = i;
        for (int s4 = 0; s4 < 64; s4++) g_vmap[s4] = ipv[g_perm[1][s4]];
    }
}

// ---------------- kernel 1: build fragment-packed bases (fwd + inv merged) --------
#define FWDN (3 * 8 * 2 * 64 * 32 * 4)   // 393216
#define INVN (2 * 128 * 4 * 32 * 4)      // 131072

__global__ __launch_bounds__(256) void build_packed(const int* __restrict__ iq,
                                                    const int* __restrict__ ik,
                                                    const int* __restrict__ iv) {
    for (int gid = blockIdx.x * blockDim.x + threadIdx.x; gid < FWDN + INVN;
         gid += gridDim.x * blockDim.x) {
        if (gid < FWDN) {
            int r    = gid & 3;
            int lane = (gid >> 2) & 31;
            int ks   = (gid >> 7) & 63;
            int vv   = (gid >> 13) & 1;
            int s    = (gid >> 14) & 7;
            int t    = gid >> 17;
            int m_local = s * 16 + (r & 1) * 8 + (lane >> 2);
            const int* ix = (t == 0) ? iq : ((t == 1) ? ik : iv);
            int f = ix[g_perm[t][m_local & 63]];
            float v0 = 0.0f, v1 = 0.0f;
            if ((f & 1) == vv) {
                int k = ks * 16 + ((r >> 1) & 1) * 8 + (lane & 3) * 2;   // n in [0,1024)
                int r1 = (f * k) & (LL - 1);
                int r2 = (r1 + f) & (LL - 1);
                float2 c1 = g_tab[r1], c2 = g_tab[r2];
                v0 = (m_local < MODES) ? c1.x : -c1.y;
                v1 = (m_local < MODES) ? c2.x : -c2.y;
            }
            uint32_t h, l;
            split2h_f(v0, v1, h, l);
            g_WfPHi[t][s][vv][ks][lane][r] = h;
            g_WfPLo[t][s][vv][ks][lane][r] = l;
        } else {
            int g2   = gid - FWDN;
            int r    = g2 & 3;
            int lane = (g2 >> 2) & 31;
            int ks   = (g2 >> 7) & 3;
            int st   = (g2 >> 9) & 127;
            int arr  = (g2 >> 16) & 1;       // 0 = cos, 1 = -sin
            int n  = st * 16 + (r & 1) * 8 + (lane >> 2);          // [0,2048)
            int k  = ks * 16 + ((r >> 1) & 1) * 8 + (lane & 3) * 2; // [0,64)
            float v0, v1;
            {
                int fb = g_perm[0][k];
                float cs = (fb == 0) ? 0.25f : 0.5f;   // 1024 * (1 or 2)/4096
                float2 c1 = g_tab[(fb * n) & (LL - 1)];
                v0 = arr ? (-cs * c1.y) : (cs * c1.x);
            }
            {
                int fb = g_perm[0][k + 1];
                float cs = (fb == 0) ? 0.25f : 0.5f;
                float2 c1 = g_tab[(fb * n) & (LL - 1)];
                v1 = arr ? (-cs * c1.y) : (cs * c1.x);
            }
            uint32_t h, l;
            split2h_f(v0, v1, h, l);
            if (arr == 0) { g_WiCcHi[st][ks][lane][r] = h; g_WiCcLo[st][ks][lane][r] = l; }
            else          { g_WiCsHi[st][ks][lane][r] = h; g_WiCsLo[st][ks][lane][r] = l; }
        }
    }
}

// ---------------- kernel 2: forward DFT (fold-by-4, coalesced staging, R15) -------
#define FWD_BUF_WORDS 2560
__global__ __launch_bounds__(512, 2) void fwd_mma(const float* __restrict__ q,
                                                  const float* __restrict__ k_,
                                                  const float* __restrict__ v_,
                                                  const int* __restrict__ iq,
                                                  const int* __restrict__ ik,
                                                  const int* __restrict__ iv) {
    extern __shared__ uint32_t dsm[];
    const int split = blockIdx.x, bh = blockIdx.y, t = blockIdx.z;
    const float* xb = ((t == 0) ? q : ((t == 1) ? k_ : v_)) + (size_t)bh * LL * DD;
    const int tid = threadIdx.x, warp = tid >> 5, lane = tid & 31;
    const int g = lane >> 2, tq = lane & 3;
    const int s = ((warp >> 1) + bh + split) & 7;   // rotated strip per warp-pair
    const int jh = warp & 1;                        // j-half
    const int cls = g_sclass[t][s & 3];
    const int vbase = (s >= 4) ? 2 : 0;
    const int p  = tid >> 4;                        // k-pair index 0..31
    const int dg = tid & 15;                        // d-group
    const int wsw = ((p >> 3) << 3) + ((p & 3) << 1) + ((p >> 2) & 1);
    const int colp = wsw ^ (dg << 1);               // producer swizzled column

#define FARR(v_, hl) (dsm + ((hl) * 4 + (v_)) * FWD_BUF_WORDS)

    float acc[4][4];
#pragma unroll
    for (int j = 0; j < 4; j++)
#pragma unroll
        for (int i = 0; i < 4; i++) acc[j][i] = 0.0f;

    const uint64_t M1 = pk2(-1.0f, -1.0f);

    for (int ch = 0; ch < 4; ch++) {
        const int nn = split * 256 + ch * 64 + 2 * p;   // n (first of pair), in [0,1024)
        {
            const int mi0 = (LL - nn) & (LL - 1);
            const int mi1 = LL - 1 - nn;
            const int dof = dg * 4;
            const float* pa  = xb + (size_t)nn * DD + dof;
            const float* pr0 = xb + (size_t)mi0 * DD + dof;
            const float* pr1 = xb + (size_t)mi1 * DD + dof;
            const float* pc  = xb + (size_t)(2048 + nn) * DD + dof;
            const float* pd0 = xb + (size_t)(2048 - nn) * DD + dof;
            const float* pd1 = xb + (size_t)(2047 - nn) * DD + dof;
            float4 x0;
            x0 = *(const float4*)(pa);
            float Aa[4] = {x0.x, x0.y, x0.z, x0.w};
            x0 = *(const float4*)(pa + DD);
            float Ab[4] = {x0.x, x0.y, x0.z, x0.w};
            x0 = *(const float4*)(pr0);
            float Ra[4] = {x0.x, x0.y, x0.z, x0.w};
            x0 = *(const float4*)(pr1);
            float Rb[4] = {x0.x, x0.y, x0.z, x0.w};
            x0 = *(const float4*)(pc);
            float Ca[4] = {x0.x, x0.y, x0.z, x0.w};
            x0 = *(const float4*)(pc + DD);
            float Cb[4] = {x0.x, x0.y, x0.z, x0.w};
            x0 = *(const float4*)(pd0);
            float Da[4] = {x0.x, x0.y, x0.z, x0.w};
            x0 = *(const float4*)(pd1);
            float Db[4] = {x0.x, x0.y, x0.z, x0.w};

            uint32_t* B0H = FARR(0, 0); uint32_t* B0L = FARR(0, 1);
            uint32_t* B1H = FARR(1, 0); uint32_t* B1L = FARR(1, 1);
            uint32_t* B2H = FARR(2, 0); uint32_t* B2L = FARR(2, 1);
            uint32_t* B3H = FARR(3, 0); uint32_t* B3L = FARR(3, 1);
#pragma unroll
            for (int i = 0; i < 4; i++) {
                uint64_t A = pk2(Aa[i], Ab[i]);
                uint64_t R = pk2(Ra[i], Rb[i]);
                uint64_t C = pk2(Ca[i], Cb[i]);
                uint64_t D = pk2(Da[i], Db[i]);
                uint64_t u = addx2(A, R);
                uint64_t wv = fmax2(R, M1, A);
                uint64_t y = addx2(C, D);
                uint64_t z = fmax2(D, M1, C);
                if (nn == 0) {   // half-weight on n=0 sample (lo half of pair)
                    float ua, ub, ya, yb;
                    unpk2(u, ua, ub); ua *= 0.5f; u = pk2(ua, ub);
                    unpk2(y, ya, yb); ya *= 0.5f; y = pk2(ya, yb);
                }
                uint64_t b0 = addx2(u, y);
                uint64_t b1 = fmax2(y, M1, u);
                uint64_t b2 = addx2(wv, z);
                uint64_t b3 = fmax2(z, M1, wv);
                const int row = dg * 4 + i;          // d index
                const int adr = row * 40 + colp;
                uint32_t h, l;
                split2h_pk(b0, h, l); B0H[adr] = h; B0L[adr] = l;
                split2h_pk(b1, h, l); B1H[adr] = h; B1L[adr] = l;
                split2h_pk(b2, h, l); B2H[adr] = h; B2L[adr] = l;
                split2h_pk(b3, h, l); B3H[adr] = h; B3L[adr] = l;
            }
        }
        __syncthreads();
        const int ksg = split * 16 + ch * 4;
#pragma unroll
        for (int ks4 = 0; ks4 < 4; ks4++) {
            if (cls != 1) {
                uint4 aH = *(const uint4*)&g_WfPHi[t][s][0][ksg + ks4][lane][0];
                uint4 aL = *(const uint4*)&g_WfPLo[t][s][0][ksg + ks4][lane][0];
                const uint32_t* BH_ = FARR(vbase + 0, 0);
                const uint32_t* BL_ = FARR(vbase + 0, 1);
#pragma unroll
                for (int j = 0; j < 4; j++) {
                    const int jg = jh * 4 + j;
                    const int rowX = jg * 8 + g;
                    const int csw = (ks4 * 8 + 2 * tq) ^ ((rowX >> 2) << 1);
                    uint2 bH = *(const uint2*)&BH_[rowX * 40 + csw];
                    uint2 bL = *(const uint2*)&BL_[rowX * 40 + csw];
                    mma16816h(acc[j], aH, bH);
                    mma16816h(acc[j], aH, bL);
                    mma16816h(acc[j], aL, bH);
                }
            }
            if (cls != 0) {
                uint4 aH = *(const uint4*)&g_WfPHi[t][s][1][ksg + ks4][lane][0];
                uint4 aL = *(const uint4*)&g_WfPLo[t][s][1][ksg + ks4][lane][0];
                const uint32_t* BH_ = FARR(vbase + 1, 0);
                const uint32_t* BL_ = FARR(vbase + 1, 1);
#pragma unroll
                for (int j = 0; j < 4; j++) {
                    const int jg = jh * 4 + j;
                    const int rowX = jg * 8 + g;
                    const int csw = (ks4 * 8 + 2 * tq) ^ ((rowX >> 2) << 1);
                    uint2 bH = *(const uint2*)&BH_[rowX * 40 + csw];
                    uint2 bL = *(const uint2*)&BL_[rowX * 40 + csw];
                    mma16816h(acc[j], aH, bH);
                    mma16816h(acc[j], aH, bL);
                    mma16816h(acc[j], aL, bH);
                }
            }
        }
        __syncthreads();
    }

    const int m0 = s * 16;
    // rank-1 correction for samples x[1024], x[3072] (added once, in split 0)
    if (split == 0) {
        const int* ix = (t == 0) ? iq : ((t == 1) ? ik : iv);
        const bool is_im = (s >= 4);
        int f0 = ix[g_perm[t][(m0 + g) & 63]];
        int f1 = ix[g_perm[t][(m0 + g + 8) & 63]];
        float s0f, s1f;
        if (!is_im) {
            s0f = (f0 & 1) ? 0.0f : (((f0 >> 1) & 1) ? -1.0f : 1.0f);
            s1f = (f1 & 1) ? 0.0f : (((f1 >> 1) & 1) ? -1.0f : 1.0f);
        } else {
            s0f = (f0 & 1) ? (((f0 & 3) == 1) ? -1.0f : 1.0f) : 0.0f;
            s1f = (f1 & 1) ? (((f1 & 3) == 1) ? -1.0f : 1.0f) : 0.0f;
        }
        const float sgn = is_im ? -1.0f : 1.0f;
#pragma unroll
        for (int j = 0; j < 4; j++) {
            const int jg = jh * 4 + j;
            int d0 = jg * 8 + 2 * tq;
            float2 u1 = *(const float2*)(xb + (size_t)1024 * DD + d0);
            float2 u3 = *(const float2*)(xb + (size_t)3072 * DD + d0);
            float uc0 = u1.x + sgn * u3.x;
            float uc1 = u1.y + sgn * u3.y;
            acc[j][0] += s0f * uc0; acc[j][1] += s0f * uc1;
            acc[j][2] += s1f * uc0; acc[j][3] += s1f * uc1;
        }
    }
#pragma unroll
    for (int j = 0; j < 4; j++) {
        const int jg = jh * 4 + j;
        float* dst = &g_F[t][split][bh][m0 + g][jg * 8 + 2 * tq];
        *(float2*)dst = make_float2(acc[j][0], acc[j][1]);
        *(float2*)(dst + 8 * DD) = make_float2(acc[j][2], acc[j][3]);
    }
#undef FARR
}

// ---------------- kernel 3: complex attention (2-way split, vectorized LDS) -------
// Conflict-free column remap (tn + 16*j) + float4 smem reads along d/n.
// Per-element FMA order identical to R15 -> bit-identical output.
#define SPA 68
__device__ __forceinline__ float4 sum_splits4(const float* base) {
    const size_t STR = (size_t)BH * MM * DD;
    float4 a = *(const float4*)(base);
#pragma unroll
    for (int s = 1; s < NSPLIT; s++) {
        float4 b = *(const float4*)(base + s * STR);
        a.x += b.x; a.y += b.y; a.z += b.z; a.w += b.w;
    }
    return a;
}

__global__ __launch_bounds__(512) void attn_kernel() {
    extern __shared__ float sm[];
    float* Ks = sm;                 // [128][68]
    float* Vs = Ks + MM * SPA;      // [128][68]
    float* Qs = Vs + MM * SPA;      // [64][68]
    float* SR = Qs + 64 * SPA;      // [32][68]
    float* SI = SR + 32 * SPA;      // [32][68]

    const int bh = blockIdx.x, ms = blockIdx.y;   // ms in {0,1}
    const int tid = threadIdx.x;

    for (int e = tid; e < MM * 16; e += 512) {
        const int r = e >> 4, d4 = (e & 15) * 4;
        float4 kk = sum_splits4(&g_F[1][0][bh][r][d4]);
        int vrow = ((r >= 64) ? 64 : 0) + __ldg(&g_vmap[r & 63]);
        float4 vv = sum_splits4(&g_F[2][0][bh][vrow][d4]);
        *(float4*)&Ks[r * SPA + d4] = kk;
        *(float4*)&Vs[r * SPA + d4] = vv;
    }
    for (int e = tid; e < 64 * 16; e += 512) {
        const int r = e >> 4, d4 = (e & 15) * 4;
        int qrow = (r < 32) ? (ms * 32 + r) : (64 + ms * 32 + (r - 32));
        float4 qq = sum_splits4(&g_F[0][0][bh][qrow][d4]);
        *(float4*)&Qs[r * SPA + d4] = qq;
    }
    __syncthreads();

    const int tm = tid >> 4;   // mode row 0..31
    const int tn = tid & 15;

    {
        float re[4], im[4];
#pragma unroll
        for (int j = 0; j < 4; j++) { re[j] = 0.f; im[j] = 0.f; }
        for (int d4 = 0; d4 < DD; d4 += 4) {
            float4 q4r = *(const float4*)&Qs[tm * SPA + d4];
            float4 q4i = *(const float4*)&Qs[(32 + tm) * SPA + d4];
            float qr[4] = {q4r.x, q4r.y, q4r.z, q4r.w};
            float qi[4] = {q4i.x, q4i.y, q4i.z, q4i.w};
#pragma unroll
            for (int j = 0; j < 4; j++) {
                const int kc = tn + 16 * j;
                float4 k4r = *(const float4*)&Ks[kc * SPA + d4];
                float4 k4i = *(const float4*)&Ks[(64 + kc) * SPA + d4];
                float kr[4] = {k4r.x, k4r.y, k4r.z, k4r.w};
                float ki[4] = {k4i.x, k4i.y, k4i.z, k4i.w};
#pragma unroll
                for (int c = 0; c < 4; c++) {
                    re[j] = fmaf(qr[c], kr[c], re[j]);
                    re[j] = fmaf(-qi[c], ki[c], re[j]);
                    im[j] = fmaf(qr[c], ki[c], im[j]);
                    im[j] = fmaf(qi[c], kr[c], im[j]);
                }
            }
        }
#pragma unroll
        for (int j = 0; j < 4; j++) {
            const float x  = re[j] * SCALE;
            const float y  = im[j] * SCALE;
            const float x2 = 2.0f * x;
            float tr, ti;
            if (fabsf(x2) > 80.0f) {
                tr = (x > 0.0f) ? 1.0f : -1.0f;
                ti = 0.0f;
            } else {
                const float y2 = 2.0f * y;
                const float dn = coshf(x2) + cosf(y2);
                tr = sinhf(x2) / dn;
                ti = sinf(y2) / dn;
            }
            SR[tm * SPA + tn + 16 * j] = tr;
            SI[tm * SPA + tn + 16 * j] = ti;
        }
    }
    __syncthreads();

    {
        float vr[4], vi[4];
#pragma unroll
        for (int j = 0; j < 4; j++) { vr[j] = 0.f; vi[j] = 0.f; }
        for (int n4 = 0; n4 < MODES; n4 += 4) {
            float4 s4r = *(const float4*)&SR[tm * SPA + n4];
            float4 s4i = *(const float4*)&SI[tm * SPA + n4];
            float sr[4] = {s4r.x, s4r.y, s4r.z, s4r.w};
            float si[4] = {s4i.x, s4i.y, s4i.z, s4i.w};
#pragma unroll
            for (int c = 0; c < 4; c++) {
                const int n = n4 + c;
#pragma unroll
                for (int j = 0; j < 4; j++) {
                    const int vc = tn + 16 * j;
                    float br = Vs[n * SPA + vc];
                    float bi = Vs[(64 + n) * SPA + vc];
                    vr[j] = fmaf(sr[c], br, vr[j]);
                    vr[j] = fmaf(-si[c], bi, vr[j]);
                    vi[j] = fmaf(sr[c], bi, vi[j]);
                    vi[j] = fmaf(si[c], br, vi[j]);
                }
            }
        }
#pragma unroll
        for (int j = 0; j < 4; j++) {
            const int vc = tn + 16 * j;
            g_V2[bh][ms * 32 + tm][vc]      = vr[j];
            g_V2[bh][64 + ms * 32 + tm][vc] = vi[j];
        }
    }
}

// ---------------- kernel 4: inverse transform (mirror trick, fp16 3-pass) ---------
#define ISC (1.0f / 1024.0f)
__global__ __launch_bounds__(256) void inv_mma(float* __restrict__ out) {
    __shared__ uint32_t BsH[64][72];
    __shared__ uint32_t BsL[64][72];
    const int nt = blockIdx.x, bh = blockIdx.y;
    const int tid = threadIdx.x, warp = tid >> 5, lane = tid & 31;
    const int g = lane >> 2, tq = lane & 3;

    {
        const int pr = tid & 63, quad = tid >> 6;
        const int w = ((pr >> 3) << 3) + ((pr & 3) << 1) + ((pr >> 2) & 1);
        const float* r0 = &g_V2[bh][2 * pr][quad * 16];
#pragma unroll
        for (int c4 = 0; c4 < 4; c4++) {
            float4 a4 = *(const float4*)(r0 + c4 * 4);
            float4 b4 = *(const float4*)(r0 + DD + c4 * 4);
            float ar[4] = {a4.x, a4.y, a4.z, a4.w};
            float br[4] = {b4.x, b4.y, b4.z, b4.w};
#pragma unroll
            for (int i = 0; i < 4; i++) {
                int d = quad * 16 + c4 * 4 + i;
                uint32_t h, l;
                split2h_f(ar[i] * ISC, br[i] * ISC, h, l);
                BsH[d][w] = h;
                BsL[d][w] = l;
            }
        }
    }
    __syncthreads();

    float accC[8][4], accS[8][4];
#pragma unroll
    for (int j = 0; j < 8; j++)
#pragma unroll
        for (int i = 0; i < 4; i++) { accC[j][i] = 0.0f; accS[j][i] = 0.0f; }

    const int st = nt * 8 + warp;
#pragma unroll
    for (int ks = 0; ks < 4; ks++) {
        uint4 aHc = *(const uint4*)&g_WiCcHi[st][ks][lane][0];
        uint4 aLc = *(const uint4*)&g_WiCcLo[st][ks][lane][0];
        uint4 aHs = *(const uint4*)&g_WiCsHi[st][ks][lane][0];
        uint4 aLs = *(const uint4*)&g_WiCsLo[st][ks][lane][0];
#pragma unroll
        for (int j = 0; j < 8; j++) {
            uint2 bHc = *(const uint2*)&BsH[j * 8 + g][ks * 8 + 2 * tq];
            uint2 bLc = *(const uint2*)&BsL[j * 8 + g][ks * 8 + 2 * tq];
            uint2 bHs = *(const uint2*)&BsH[j * 8 + g][(ks + 4) * 8 + 2 * tq];
            uint2 bLs = *(const uint2*)&BsL[j * 8 + g][(ks + 4) * 8 + 2 * tq];
            mma16816h(accC[j], aHc, bHc);
            mma16816h(accC[j], aHc, bLc);
            mma16816h(accC[j], aLc, bHc);
            mma16816h(accS[j], aHs, bHs);
            mma16816h(accS[j], aHs, bLs);
            mma16816h(accS[j], aLs, bHs);
        }
    }

    const int n0r = nt * 128 + warp * 16;
    float* ob = out + (size_t)bh * LL * DD;
#pragma unroll
    for (int j = 0; j < 8; j++) {
        const int d0 = j * 8 + 2 * tq;
        const int na = n0r + g, nb = n0r + g + 8;
        *(float2*)(ob + (size_t)na * DD + d0) =
            make_float2(accC[j][0] + accS[j][0], accC[j][1] + accS[j][1]);
        if (na != 0)
            *(float2*)(ob + (size_t)(LL - na) * DD + d0) =
                make_float2(accC[j][0] - accS[j][0], accC[j][1] - accS[j][1]);
        *(float2*)(ob + (size_t)nb * DD + d0) =
            make_float2(accC[j][2] + accS[j][2], accC[j][3] + accS[j][3]);
        *(float2*)(ob + (size_t)(LL - nb) * DD + d0) =
            make_float2(accC[j][2] - accS[j][2], accC[j][3] - accS[j][3]);
    }
    // out[2048] = sum_k c_k * (-1)^{f_k} * Vr[k][d]   (sin term = 0)
    if (nt == 0 && tid < 64) {
        const int d = tid;
        float sum = 0.0f;
#pragma unroll 8
        for (int k = 0; k < 64; k++) {
            int fb = g_perm[0][k];
            float c = (fb == 0) ? (1.0f / 4096.0f) : (2.0f / 4096.0f);
            float sg = (fb & 1) ? -c : c;
            sum += sg * g_V2[bh][k][d];
        }
        ob[(size_t)2048 * DD + d] = sum;
    }
}

// ---------------- entry point ----------------
extern "C" void kernel_launch(void* const* d_in, const int* in_sizes, int n_in,
                              void* d_out, int out_size) {
    const float* q  = (const float*)d_in[0];
    const float* k  = (const float*)d_in[1];
    const float* v  = (const float*)d_in[2];
    const int* iq   = (const int*)d_in[3];
    const int* ik   = (const int*)d_in[4];
    const int* iv   = (const int*)d_in[5];
    float* out      = (float*)d_out;

    tab_kernel<<<16, 256>>>(iq, ik, iv);            // idx 0
    build_packed<<<1024, 256>>>(iq, ik, iv);        // idx 1

    const int fwd_smem = 8 * FWD_BUF_WORDS * 4;   // 81920 B
    cudaFuncSetAttribute(fwd_mma, cudaFuncAttributeMaxDynamicSharedMemorySize, fwd_smem);
    fwd_mma<<<dim3(NSPLIT, BH, 3), 512, fwd_smem>>>(q, k, v, iq, ik, iv);   // idx 2

    const int attn_smem = (2 * MM + 64 + 2 * 32) * SPA * (int)sizeof(float);  // 104448 B
    cudaFuncSetAttribute(attn_kernel, cudaFuncAttributeMaxDynamicSharedMemorySize, attn_smem);
    attn_kernel<<<dim3(BH, 2), 512, attn_smem>>>();                          // idx 3

    inv_mma<<<dim3(16, 64), 256>>>(out);                                     // idx 4
}